// round 7
// baseline (speedup 1.0000x reference)
#include <cuda_runtime.h>
#include <cuda_fp16.h>
#include <cstdint>

#define N_NODES 50000
#define E_EDGES 800000
#define IN_CH   128
#define OUT_CH  64
#define BN_EPS  1e-5f
#define MAXDEG  64

// ---------------- scratch (device globals; no allocation allowed) ----------
__device__ uint4 g_h16[(size_t)N_NODES * 8];           // hs in fp16: 64 half = 8 uint4/row
__device__ float g_agg[(size_t)N_NODES * OUT_CH];      // tanh(agg+bias) activations
__device__ int   g_deg[N_NODES];                       // in-degree (excl. self-loop)
__device__ int   g_bucket[(size_t)N_NODES * MAXDEG];   // src ids grouped by dst
__device__ float g_sum[OUT_CH];
__device__ float g_sumsq[OUT_CH];
__device__ int   g_is64;                               // 1 if edge_index is int64

// ---------------- helpers ----------------------------------------------------
__device__ __forceinline__ unsigned long long rep2(float x) {
    unsigned long long r;
    asm("mov.b64 %0, {%1, %1};" : "=l"(r) : "f"(x));
    return r;
}
__device__ __forceinline__ void ffma2(unsigned long long& d,
                                      unsigned long long a,
                                      unsigned long long b) {
    asm("fma.rn.f32x2 %0, %1, %2, %0;" : "+l"(d) : "l"(a), "l"(b));
}
union F2U { unsigned long long u; float2 f; };

// ---------------- K1: dtype detect + zero deg/stats -------------------------
__global__ void init_detect_kernel(const long long* __restrict__ p,
                                   int Nnodes, int n64) {
    int i = blockIdx.x * blockDim.x + threadIdx.x;
    if (i < Nnodes) g_deg[i] = 0;
    if (i < OUT_CH) { g_sum[i] = 0.f; g_sumsq[i] = 0.f; }
    if (blockIdx.x == 0) {
        __shared__ int s_ok;
        if (threadIdx.x == 0) s_ok = 1;
        __syncthreads();
        int chk = n64 < 128 ? n64 : 128;
        bool bad = false;
        if ((int)threadIdx.x < chk) {
            long long v = p[threadIdx.x];
            bad = (v < 0) || (v >= (long long)Nnodes);
        }
        unsigned m = __ballot_sync(0xffffffffu, bad);
        if (m && (threadIdx.x & 31) == 0) atomicAnd(&s_ok, 0);
        __syncthreads();
        if (threadIdx.x == 0) g_is64 = s_ok;
    }
}

__device__ __forceinline__ int load_idx(const void* base, int i, int is64) {
    if (is64) return (int)((const long long*)base)[i];
    return ((const int*)base)[i];
}

// ---------------- K2: counting-sort edges into per-dst buckets --------------
__global__ void place_kernel(const void* __restrict__ ei, int E, int N) {
    int e = blockIdx.x * blockDim.x + threadIdx.x;
    if (e >= E) return;
    int is64 = g_is64;
    int s = load_idx(ei, e, is64);
    int d = load_idx(ei, E + e, is64);
    if ((unsigned)s >= (unsigned)N || (unsigned)d >= (unsigned)N) return;
    int pos = atomicAdd(&g_deg[d], 1);
    if (pos < MAXDEG) g_bucket[(size_t)d * MAXDEG + pos] = s;
}

// ---------------- K3: GEMM hs = (x @ W) * dinv[row], fp16 output ------------
// fp32 math via packed fma.rn.f32x2 (FFMA2), accumulators as f32x2 pairs.
__global__ void gemm_kernel(const float* __restrict__ x,
                            const float* __restrict__ W, int N) {
    extern __shared__ float sm[];
    float* Ws = sm;                     // 128*64 floats
    float* xs = sm + IN_CH * OUT_CH;    // 64*132 floats

    const int tid = threadIdx.x;
    const int rowbase = blockIdx.x * 64;

#pragma unroll
    for (int i = 0; i < 8; i++) {
        int idx = tid + i * 256;
        ((float4*)Ws)[idx] = ((const float4*)W)[idx];
    }
#pragma unroll
    for (int i = 0; i < 8; i++) {
        int idx = tid + i * 256;
        int r  = idx >> 5;
        int kc = idx & 31;
        float4 v = make_float4(0.f, 0.f, 0.f, 0.f);
        int gr = rowbase + r;
        if (gr < N) v = ((const float4*)(x + (size_t)gr * IN_CH))[kc];
        *(float4*)(xs + r * 132 + kc * 4) = v;
    }
    __syncthreads();

    const int tx = tid & 15;   // cols 4tx..4tx+3 (two f32x2 pairs)
    const int ty = tid >> 4;   // rows 4ty..4ty+3

    unsigned long long acc2[4][2];
#pragma unroll
    for (int r = 0; r < 4; r++) { acc2[r][0] = 0ull; acc2[r][1] = 0ull; }

#pragma unroll 8
    for (int k4 = 0; k4 < IN_CH / 4; k4++) {
        float4 a[4];
        ulonglong2 b[4];
#pragma unroll
        for (int r = 0; r < 4; r++)
            a[r] = *(const float4*)(xs + (4 * ty + r) * 132 + k4 * 4);
#pragma unroll
        for (int j = 0; j < 4; j++)
            b[j] = *(const ulonglong2*)(Ws + (k4 * 4 + j) * OUT_CH + tx * 4);
        const float* af = (const float*)a;
#pragma unroll
        for (int r = 0; r < 4; r++)
#pragma unroll
            for (int j = 0; j < 4; j++) {
                unsigned long long ar = rep2(af[r * 4 + j]);
                ffma2(acc2[r][0], ar, b[j].x);
                ffma2(acc2[r][1], ar, b[j].y);
            }
    }

#pragma unroll
    for (int r = 0; r < 4; r++) {
        int gr = rowbase + 4 * ty + r;
        if (gr < N) {
            float di = rsqrtf((float)(g_deg[gr] + 1));  // +1 self-loop
            F2U lo, hi;
            lo.u = acc2[r][0]; hi.u = acc2[r][1];
            __half2 p[2];
            p[0] = __floats2half2_rn(lo.f.x * di, lo.f.y * di);
            p[1] = __floats2half2_rn(hi.f.x * di, hi.f.y * di);
            *((uint2*)g_h16 + (size_t)gr * 16 + tx) = *(uint2*)p;
        }
    }
}

// ---------------- K4: gather-aggregate + tanh + fused BN stats ---------------
// One node per warp; lane l owns fp16 chunk (l&7) [8 channels]; lane-group
// (l>>3) walks srcs 4 at a time so one LDG.128 fetches 4 neighbor rows.
// agg = dinv * (own + sum srcs)  (hs already carries dinv[src]).
// a = tanh(agg + bias) written to g_agg; per-thread channel sums accumulate
// across a grid-stride loop and flush once per block.
__global__ void aggregate_kernel(const float* __restrict__ bias, int N) {
    __shared__ float sh[OUT_CH];
    __shared__ float shq[OUT_CH];
    const int tid  = threadIdx.x;
    const int lane = tid & 31;
    const int warp = tid >> 5;
    const int chunk = lane & 7;
    const int grp   = lane >> 3;

    if (tid < OUT_CH) { sh[tid] = 0.f; shq[tid] = 0.f; }
    __syncthreads();

    float bs[8];
#pragma unroll
    for (int k = 0; k < 8; k++) bs[k] = __ldg(bias + chunk * 8 + k);

    float ssum[8], ssq[8];
#pragma unroll
    for (int k = 0; k < 8; k++) { ssum[k] = 0.f; ssq[k] = 0.f; }

    const int wstride = gridDim.x * (blockDim.x >> 5);
    for (int n = blockIdx.x * (blockDim.x >> 5) + warp; n < N; n += wstride) {
        int deg = g_deg[n];
        float dinv = rsqrtf((float)(deg + 1));
        int dd = deg < MAXDEG ? deg : MAXDEG;
        const int* bk = g_bucket + (size_t)n * MAXDEG;

        float acc[8];
#pragma unroll
        for (int k = 0; k < 8; k++) acc[k] = 0.f;

        int nb = (dd + 3) >> 2;
        for (int t = 0; t < nb; t++) {
            int idx = t * 4 + grp;
            if (idx < dd) {
                int s = bk[idx];
                uint4 q = g_h16[(size_t)s * 8 + chunk];
                float2 f0 = __half22float2(*(__half2*)&q.x);
                float2 f1 = __half22float2(*(__half2*)&q.y);
                float2 f2 = __half22float2(*(__half2*)&q.z);
                float2 f3 = __half22float2(*(__half2*)&q.w);
                acc[0] += f0.x; acc[1] += f0.y;
                acc[2] += f1.x; acc[3] += f1.y;
                acc[4] += f2.x; acc[5] += f2.y;
                acc[6] += f3.x; acc[7] += f3.y;
            }
        }
        // cross-group reduce: sum over lanes {l, l^8, l^16, l^24}
#pragma unroll
        for (int k = 0; k < 8; k++) {
            acc[k] += __shfl_xor_sync(0xffffffffu, acc[k], 8);
            acc[k] += __shfl_xor_sync(0xffffffffu, acc[k], 16);
        }
        if (grp == 0) {
            // own row (self-loop)
            uint4 q = g_h16[(size_t)n * 8 + chunk];
            float2 f0 = __half22float2(*(__half2*)&q.x);
            float2 f1 = __half22float2(*(__half2*)&q.y);
            float2 f2 = __half22float2(*(__half2*)&q.z);
            float2 f3 = __half22float2(*(__half2*)&q.w);
            acc[0] += f0.x; acc[1] += f0.y;
            acc[2] += f1.x; acc[3] += f1.y;
            acc[4] += f2.x; acc[5] += f2.y;
            acc[6] += f3.x; acc[7] += f3.y;

            float a[8];
#pragma unroll
            for (int k = 0; k < 8; k++) {
                a[k] = tanhf(acc[k] * dinv + bs[k]);
                ssum[k] += a[k];
                ssq[k]  += a[k] * a[k];
            }
            float* dst = g_agg + (size_t)n * OUT_CH + chunk * 8;
            *(float4*)dst       = make_float4(a[0], a[1], a[2], a[3]);
            *(float4*)(dst + 4) = make_float4(a[4], a[5], a[6], a[7]);
        }
    }

    if (grp == 0) {
#pragma unroll
        for (int k = 0; k < 8; k++) {
            atomicAdd(&sh[chunk * 8 + k], ssum[k]);
            atomicAdd(&shq[chunk * 8 + k], ssq[k]);
        }
    }
    __syncthreads();
    if (tid < OUT_CH) {
        atomicAdd(&g_sum[tid], sh[tid]);
        atomicAdd(&g_sumsq[tid], shq[tid]);
    }
}

// ---------------- K5: apply fused BN, write out ------------------------------
__global__ void norm_kernel(const float* __restrict__ gamma,
                            const float* __restrict__ beta,
                            float* __restrict__ out, int N, float invN) {
    int t = blockIdx.x * blockDim.x + threadIdx.x;
    if (t >= N * 16) return;
    int c4 = (t & 15) << 2;

    float4 su = *(const float4*)(g_sum + c4);
    float4 sq = *(const float4*)(g_sumsq + c4);
    float4 gm = *(const float4*)(gamma + c4);
    float4 bt = *(const float4*)(beta + c4);

    float m0 = su.x * invN, m1 = su.y * invN, m2 = su.z * invN, m3 = su.w * invN;
    float v0 = fmaxf(sq.x * invN - m0 * m0, 0.f);
    float v1 = fmaxf(sq.y * invN - m1 * m1, 0.f);
    float v2 = fmaxf(sq.z * invN - m2 * m2, 0.f);
    float v3 = fmaxf(sq.w * invN - m3 * m3, 0.f);
    float s0 = gm.x * rsqrtf(v0 + BN_EPS);
    float s1 = gm.y * rsqrtf(v1 + BN_EPS);
    float s2 = gm.z * rsqrtf(v2 + BN_EPS);
    float s3 = gm.w * rsqrtf(v3 + BN_EPS);

    float4 a = *(const float4*)(g_agg + ((size_t)(t >> 4)) * OUT_CH + c4);
    float4 o;
    o.x = (a.x - m0) * s0 + bt.x;
    o.y = (a.y - m1) * s1 + bt.y;
    o.z = (a.z - m2) * s2 + bt.z;
    o.w = (a.w - m3) * s3 + bt.w;
    ((float4*)out)[t] = o;
}

// ---------------- launch -----------------------------------------------------
extern "C" void kernel_launch(void* const* d_in, const int* in_sizes, int n_in,
                              void* d_out, int out_size) {
    const float* x     = (const float*)d_in[0];
    const void*  ei    = d_in[1];                 // int32 or int64, detected
    const float* W     = (const float*)d_in[2];
    const float* bias  = (const float*)d_in[3];
    const float* gamma = (const float*)d_in[4];
    const float* beta  = (const float*)d_in[5];
    float*       out   = (float*)d_out;

    int N = in_sizes[0] / IN_CH;   // 50000
    if (N > N_NODES) N = N_NODES;
    int E = in_sizes[1] / 2;       // 800000

    int smem = (IN_CH * OUT_CH + 64 * 132) * (int)sizeof(float);  // 66560 B
    cudaFuncSetAttribute(gemm_kernel,
                         cudaFuncAttributeMaxDynamicSharedMemorySize, smem);

    init_detect_kernel<<<(N + 255) / 256, 256>>>((const long long*)ei, N,
                                                 in_sizes[1] / 2);
    place_kernel<<<(E + 255) / 256, 256>>>(ei, E, N);
    gemm_kernel<<<(N + 63) / 64, 256, smem>>>(x, W, N);
    aggregate_kernel<<<296, 512>>>(bias, N);
    norm_kernel<<<(N * 16 + 255) / 256, 256>>>(gamma, beta, out, N,
                                               1.f / (float)N);
}

// round 8
// speedup vs baseline: 1.1286x; 1.1286x over previous
#include <cuda_runtime.h>
#include <cuda_fp16.h>
#include <cstdint>

#define N_NODES 50000
#define E_EDGES 800000
#define IN_CH   128
#define OUT_CH  64
#define BN_EPS  1e-5f
#define MAXDEG  64

// ---------------- scratch (device globals; no allocation allowed) ----------
__device__ unsigned g_h16[(size_t)N_NODES * 32];       // hs fp16: 64 half = 32 u32/row
__device__ float g_agg[(size_t)N_NODES * OUT_CH];      // tanh(agg+bias) activations
__device__ int   g_deg[N_NODES];                       // in-degree (excl. self-loop)
__device__ int   g_bucket[(size_t)N_NODES * MAXDEG];   // src ids grouped by dst
__device__ float g_sum[OUT_CH];
__device__ float g_sumsq[OUT_CH];
__device__ int   g_is64;                               // 1 if edge_index is int64

// ---------------- helpers ----------------------------------------------------
__device__ __forceinline__ unsigned long long rep2(float x) {
    unsigned long long r;
    asm("mov.b64 %0, {%1, %1};" : "=l"(r) : "f"(x));
    return r;
}
__device__ __forceinline__ void ffma2(unsigned long long& d,
                                      unsigned long long a,
                                      unsigned long long b) {
    asm("fma.rn.f32x2 %0, %1, %2, %0;" : "+l"(d) : "l"(a), "l"(b));
}
union F2U { unsigned long long u; float2 f; };

// ---------------- K1: dtype detect + zero deg/stats -------------------------
__global__ void init_detect_kernel(const long long* __restrict__ p,
                                   int Nnodes, int n64) {
    int i = blockIdx.x * blockDim.x + threadIdx.x;
    if (i < Nnodes) g_deg[i] = 0;
    if (i < OUT_CH) { g_sum[i] = 0.f; g_sumsq[i] = 0.f; }
    if (blockIdx.x == 0) {
        __shared__ int s_ok;
        if (threadIdx.x == 0) s_ok = 1;
        __syncthreads();
        int chk = n64 < 128 ? n64 : 128;
        bool bad = false;
        if ((int)threadIdx.x < chk) {
            long long v = p[threadIdx.x];
            bad = (v < 0) || (v >= (long long)Nnodes);
        }
        unsigned m = __ballot_sync(0xffffffffu, bad);
        if (m && (threadIdx.x & 31) == 0) atomicAnd(&s_ok, 0);
        __syncthreads();
        if (threadIdx.x == 0) g_is64 = s_ok;
    }
}

__device__ __forceinline__ int load_idx(const void* base, int i, int is64) {
    if (is64) return (int)((const long long*)base)[i];
    return ((const int*)base)[i];
}

// ---------------- K2: counting-sort edges into per-dst buckets --------------
__global__ void place_kernel(const void* __restrict__ ei, int E, int N) {
    int e = blockIdx.x * blockDim.x + threadIdx.x;
    if (e >= E) return;
    int is64 = g_is64;
    int s = load_idx(ei, e, is64);
    int d = load_idx(ei, E + e, is64);
    if ((unsigned)s >= (unsigned)N || (unsigned)d >= (unsigned)N) return;
    int pos = atomicAdd(&g_deg[d], 1);
    if (pos < MAXDEG) g_bucket[(size_t)d * MAXDEG + pos] = s;
}

// ---------------- K3: GEMM hs = (x @ W) * dinv[row], fp16 output ------------
// fp32 math via packed fma.rn.f32x2 (FFMA2), accumulators as f32x2 pairs.
__global__ void gemm_kernel(const float* __restrict__ x,
                            const float* __restrict__ W, int N) {
    extern __shared__ float sm[];
    float* Ws = sm;                     // 128*64 floats
    float* xs = sm + IN_CH * OUT_CH;    // 64*132 floats

    const int tid = threadIdx.x;
    const int rowbase = blockIdx.x * 64;

#pragma unroll
    for (int i = 0; i < 8; i++) {
        int idx = tid + i * 256;
        ((float4*)Ws)[idx] = ((const float4*)W)[idx];
    }
#pragma unroll
    for (int i = 0; i < 8; i++) {
        int idx = tid + i * 256;
        int r  = idx >> 5;
        int kc = idx & 31;
        float4 v = make_float4(0.f, 0.f, 0.f, 0.f);
        int gr = rowbase + r;
        if (gr < N) v = ((const float4*)(x + (size_t)gr * IN_CH))[kc];
        *(float4*)(xs + r * 132 + kc * 4) = v;
    }
    __syncthreads();

    const int tx = tid & 15;   // cols 4tx..4tx+3 (two f32x2 pairs)
    const int ty = tid >> 4;   // rows 4ty..4ty+3

    unsigned long long acc2[4][2];
#pragma unroll
    for (int r = 0; r < 4; r++) { acc2[r][0] = 0ull; acc2[r][1] = 0ull; }

#pragma unroll 8
    for (int k4 = 0; k4 < IN_CH / 4; k4++) {
        float4 a[4];
        ulonglong2 b[4];
#pragma unroll
        for (int r = 0; r < 4; r++)
            a[r] = *(const float4*)(xs + (4 * ty + r) * 132 + k4 * 4);
#pragma unroll
        for (int j = 0; j < 4; j++)
            b[j] = *(const ulonglong2*)(Ws + (k4 * 4 + j) * OUT_CH + tx * 4);
        const float* af = (const float*)a;
#pragma unroll
        for (int r = 0; r < 4; r++)
#pragma unroll
            for (int j = 0; j < 4; j++) {
                unsigned long long ar = rep2(af[r * 4 + j]);
                ffma2(acc2[r][0], ar, b[j].x);
                ffma2(acc2[r][1], ar, b[j].y);
            }
    }

#pragma unroll
    for (int r = 0; r < 4; r++) {
        int gr = rowbase + 4 * ty + r;
        if (gr < N) {
            float di = rsqrtf((float)(g_deg[gr] + 1));  // +1 self-loop
            F2U lo, hi;
            lo.u = acc2[r][0]; hi.u = acc2[r][1];
            __half2 p[2];
            p[0] = __floats2half2_rn(lo.f.x * di, lo.f.y * di);
            p[1] = __floats2half2_rn(hi.f.x * di, hi.f.y * di);
            *((uint2*)g_h16 + (size_t)gr * 16 + tx) = *(uint2*)p;
        }
    }
}

// ---------------- K4: gather-aggregate + tanh + fused BN stats ---------------
// One warp per node (grid-stride); lane l owns channels {2l, 2l+1} (one half2,
// 4B -> a neighbor row gather is ONE 128B coalesced wavefront). Bucket walked
// 8 srcs at a time: 2 uniform int4 loads + 8 independent half2 gathers in
// flight per lane (high MLP). All lanes run the tanh/store epilogue; BN
// channel sums live in 4 registers per lane and flush once per block.
__global__ void aggregate_kernel(const float* __restrict__ bias, int N) {
    __shared__ float sh[OUT_CH];
    __shared__ float shq[OUT_CH];
    const int tid  = threadIdx.x;
    const int lane = tid & 31;
    const int wib  = tid >> 5;                         // warp-in-block

    if (tid < OUT_CH) { sh[tid] = 0.f; shq[tid] = 0.f; }
    __syncthreads();

    const float b0 = __ldg(bias + 2 * lane);
    const float b1 = __ldg(bias + 2 * lane + 1);
    float s0 = 0.f, s1 = 0.f, q0 = 0.f, q1 = 0.f;

    const int nwarps = gridDim.x * (blockDim.x >> 5);
    for (int n = blockIdx.x * (blockDim.x >> 5) + wib; n < N; n += nwarps) {
        const int deg = g_deg[n];
        const float dinv = rsqrtf((float)(deg + 1));
        const int dd = deg < MAXDEG ? deg : MAXDEG;
        const int* bk = g_bucket + (size_t)n * MAXDEG;

        // own row (self-loop)
        float2 acc = __half22float2(
            *(const __half2*)&g_h16[(size_t)n * 32 + lane]);

        int j = 0;
        for (; j + 8 <= dd; j += 8) {
            int4 sa = *(const int4*)(bk + j);
            int4 sb = *(const int4*)(bk + j + 4);
            unsigned v0 = g_h16[(size_t)sa.x * 32 + lane];
            unsigned v1 = g_h16[(size_t)sa.y * 32 + lane];
            unsigned v2 = g_h16[(size_t)sa.z * 32 + lane];
            unsigned v3 = g_h16[(size_t)sa.w * 32 + lane];
            unsigned v4 = g_h16[(size_t)sb.x * 32 + lane];
            unsigned v5 = g_h16[(size_t)sb.y * 32 + lane];
            unsigned v6 = g_h16[(size_t)sb.z * 32 + lane];
            unsigned v7 = g_h16[(size_t)sb.w * 32 + lane];
            float2 f0 = __half22float2(*(__half2*)&v0);
            float2 f1 = __half22float2(*(__half2*)&v1);
            float2 f2 = __half22float2(*(__half2*)&v2);
            float2 f3 = __half22float2(*(__half2*)&v3);
            float2 f4 = __half22float2(*(__half2*)&v4);
            float2 f5 = __half22float2(*(__half2*)&v5);
            float2 f6 = __half22float2(*(__half2*)&v6);
            float2 f7 = __half22float2(*(__half2*)&v7);
            acc.x += (f0.x + f1.x) + (f2.x + f3.x) + (f4.x + f5.x) + (f6.x + f7.x);
            acc.y += (f0.y + f1.y) + (f2.y + f3.y) + (f4.y + f5.y) + (f6.y + f7.y);
        }
        if (j + 4 <= dd) {
            int4 sa = *(const int4*)(bk + j);
            unsigned v0 = g_h16[(size_t)sa.x * 32 + lane];
            unsigned v1 = g_h16[(size_t)sa.y * 32 + lane];
            unsigned v2 = g_h16[(size_t)sa.z * 32 + lane];
            unsigned v3 = g_h16[(size_t)sa.w * 32 + lane];
            float2 f0 = __half22float2(*(__half2*)&v0);
            float2 f1 = __half22float2(*(__half2*)&v1);
            float2 f2 = __half22float2(*(__half2*)&v2);
            float2 f3 = __half22float2(*(__half2*)&v3);
            acc.x += (f0.x + f1.x) + (f2.x + f3.x);
            acc.y += (f0.y + f1.y) + (f2.y + f3.y);
            j += 4;
        }
        for (; j < dd; j++) {
            int s = bk[j];
            float2 f = __half22float2(
                *(const __half2*)&g_h16[(size_t)s * 32 + lane]);
            acc.x += f.x;
            acc.y += f.y;
        }

        float a0 = tanhf(acc.x * dinv + b0);
        float a1 = tanhf(acc.y * dinv + b1);
        *(float2*)(g_agg + (size_t)n * OUT_CH + 2 * lane) = make_float2(a0, a1);
        s0 += a0; q0 += a0 * a0;
        s1 += a1; q1 += a1 * a1;
    }

    atomicAdd(&sh[2 * lane],      s0);
    atomicAdd(&sh[2 * lane + 1],  s1);
    atomicAdd(&shq[2 * lane],     q0);
    atomicAdd(&shq[2 * lane + 1], q1);
    __syncthreads();
    if (tid < OUT_CH) {
        atomicAdd(&g_sum[tid], sh[tid]);
        atomicAdd(&g_sumsq[tid], shq[tid]);
    }
}

// ---------------- K5: apply fused BN, write out ------------------------------
__global__ void norm_kernel(const float* __restrict__ gamma,
                            const float* __restrict__ beta,
                            float* __restrict__ out, int N, float invN) {
    int t = blockIdx.x * blockDim.x + threadIdx.x;
    if (t >= N * 16) return;
    int c4 = (t & 15) << 2;

    float4 su = *(const float4*)(g_sum + c4);
    float4 sq = *(const float4*)(g_sumsq + c4);
    float4 gm = *(const float4*)(gamma + c4);
    float4 bt = *(const float4*)(beta + c4);

    float m0 = su.x * invN, m1 = su.y * invN, m2 = su.z * invN, m3 = su.w * invN;
    float v0 = fmaxf(sq.x * invN - m0 * m0, 0.f);
    float v1 = fmaxf(sq.y * invN - m1 * m1, 0.f);
    float v2 = fmaxf(sq.z * invN - m2 * m2, 0.f);
    float v3 = fmaxf(sq.w * invN - m3 * m3, 0.f);
    float s0 = gm.x * rsqrtf(v0 + BN_EPS);
    float s1 = gm.y * rsqrtf(v1 + BN_EPS);
    float s2 = gm.z * rsqrtf(v2 + BN_EPS);
    float s3 = gm.w * rsqrtf(v3 + BN_EPS);

    float4 a = *(const float4*)(g_agg + ((size_t)(t >> 4)) * OUT_CH + c4);
    float4 o;
    o.x = (a.x - m0) * s0 + bt.x;
    o.y = (a.y - m1) * s1 + bt.y;
    o.z = (a.z - m2) * s2 + bt.z;
    o.w = (a.w - m3) * s3 + bt.w;
    ((float4*)out)[t] = o;
}

// ---------------- launch -----------------------------------------------------
extern "C" void kernel_launch(void* const* d_in, const int* in_sizes, int n_in,
                              void* d_out, int out_size) {
    const float* x     = (const float*)d_in[0];
    const void*  ei    = d_in[1];                 // int32 or int64, detected
    const float* W     = (const float*)d_in[2];
    const float* bias  = (const float*)d_in[3];
    const float* gamma = (const float*)d_in[4];
    const float* beta  = (const float*)d_in[5];
    float*       out   = (float*)d_out;

    int N = in_sizes[0] / IN_CH;   // 50000
    if (N > N_NODES) N = N_NODES;
    int E = in_sizes[1] / 2;       // 800000

    int smem = (IN_CH * OUT_CH + 64 * 132) * (int)sizeof(float);  // 66560 B
    cudaFuncSetAttribute(gemm_kernel,
                         cudaFuncAttributeMaxDynamicSharedMemorySize, smem);

    init_detect_kernel<<<(N + 255) / 256, 256>>>((const long long*)ei, N,
                                                 in_sizes[1] / 2);
    place_kernel<<<(E + 255) / 256, 256>>>(ei, E, N);
    gemm_kernel<<<(N + 63) / 64, 256, smem>>>(x, W, N);
    aggregate_kernel<<<1184, 256>>>(bias, N);       // 9472 warps, ~5 nodes/warp
    norm_kernel<<<(N * 16 + 255) / 256, 256>>>(gamma, beta, out, N,
                                               1.f / (float)N);
}